// round 13
// baseline (speedup 1.0000x reference)
#include <cuda_runtime.h>
#include <cuda_fp16.h>
#include <cstdint>

#define N_NODES 100000
#define N_EDGES 3200000
#define IN_DIM  128
#define HID     32
#define OUT     12
#define H2P     16                                   // padded h2 row (halfs)
#define SCAN_B  1024
#define N_SCANB ((N_NODES + SCAN_B - 1) / SCAN_B)    // 98
#define GEMM1_BLOCKS ((N_NODES + 127) / 128)         // 782 (128 nodes/block)
#define EV_BLOCKS    ((N_EDGES / 4 + 255) / 256)     // 3125 (4 edges/thread)

// ---------------- scratch (allocation-free: __device__ globals) ----------------
__device__ __half g_h1  [N_NODES * HID];   // feat @ W1 (fp16)
__device__ __half g_h2  [N_NODES * H2P];   // layer-1 out @ W2 (fp16, padded rows)
__device__ int    g_cnt [N_NODES];
__device__ int    g_off [N_NODES];
__device__ int    g_rank[N_EDGES];         // edge rank within its dst bucket
__device__ int    g_bin [N_EDGES];         // src ids grouped by dst
__device__ int    g_part[128];

// packed f32x2 FMA (sm_10x): d = a*b + c on two fp32 lanes in one FMA-pipe slot
__device__ __forceinline__ void ffma2(unsigned long long& acc,
                                      unsigned long long a,
                                      unsigned long long b) {
    asm("fma.rn.f32x2 %0, %1, %2, %0;" : "+l"(acc) : "l"(a), "l"(b));
}
__device__ __forceinline__ unsigned long long bcast2(float f) {
    unsigned long long r;
    unsigned u = __float_as_uint(f);
    asm("mov.b64 %0, {%1, %1};" : "=l"(r) : "r"(u));
    return r;
}

// ---------------- count + rank: atomicAdd return value IS the bucket rank ----------------
__global__ void count_kernel(const int* __restrict__ dst, int* __restrict__ cnt,
                             int* __restrict__ rank) {
    int i = blockIdx.x * blockDim.x + threadIdx.x;
    if (i >= N_EDGES / 4) return;
    int4 d4 = reinterpret_cast<const int4*>(dst)[i];
    int4 r4;
    r4.x = atomicAdd(cnt + d4.x, 1);
    r4.y = atomicAdd(cnt + d4.y, 1);
    r4.z = atomicAdd(cnt + d4.z, 1);
    r4.w = atomicAdd(cnt + d4.w, 1);
    reinterpret_cast<int4*>(rank)[i] = r4;
}

// ---------------- scanA: per-block exclusive scan + block totals ----------------
__global__ void scanA_kernel(const int* __restrict__ cnt,
                             int* __restrict__ off, int* __restrict__ part) {
    __shared__ int wsum[32];
    int i = blockIdx.x * SCAN_B + threadIdx.x;
    int lane = threadIdx.x & 31, w = threadIdx.x >> 5;
    int v = (i < N_NODES) ? cnt[i] : 0;
    int x = v;
    #pragma unroll
    for (int d = 1; d < 32; d <<= 1) {
        int y = __shfl_up_sync(~0u, x, d);
        if (lane >= d) x += y;
    }
    if (lane == 31) wsum[w] = x;
    __syncthreads();
    if (w == 0) {
        int s = wsum[lane];
        #pragma unroll
        for (int d = 1; d < 32; d <<= 1) {
            int y = __shfl_up_sync(~0u, s, d);
            if (lane >= d) s += y;
        }
        wsum[lane] = s;
    }
    __syncthreads();
    int base = (w > 0) ? wsum[w - 1] : 0;
    if (i < N_NODES) off[i] = base + x - v;
    if (threadIdx.x == SCAN_B - 1) part[blockIdx.x] = base + x;
}

// ---------------- scanC: add prefix of block totals ----------------
__global__ void scanC_kernel(int* __restrict__ off, const int* __restrict__ part) {
    __shared__ int ws[4];
    __shared__ int sbase;
    int t = threadIdx.x;
    if (t < 128) {
        int v = (t < blockIdx.x && t < N_SCANB) ? part[t] : 0;
        #pragma unroll
        for (int d = 16; d >= 1; d >>= 1) v += __shfl_xor_sync(~0u, v, d);
        if ((t & 31) == 0) ws[t >> 5] = v;
    }
    __syncthreads();
    if (t == 0) sbase = ws[0] + ws[1] + ws[2] + ws[3];
    __syncthreads();
    int i = blockIdx.x * SCAN_B + t;
    if (i < N_NODES) off[i] += sbase;
}

// ---------------- fused: gemm1 (4-node register tile, FFMA2) || bin (atomic-free) ----------------
__global__ void fusedB_kernel(const float* __restrict__ feat,
                              const float* __restrict__ W1,
                              __half* __restrict__ h1,
                              const int* __restrict__ src,
                              const int* __restrict__ dst,
                              const int* __restrict__ rank,
                              const int* __restrict__ off,
                              int* __restrict__ bin) {
    __shared__ float sW[IN_DIM * HID];               // 16 KB (gemm branch only)
    int tid = threadIdx.x;
    if (blockIdx.x < GEMM1_BLOCKS) {
        for (int i = tid; i < IN_DIM * HID; i += 256) sW[i] = W1[i];
        __syncthreads();
        int g  = tid >> 3;                            // 0..31 node group
        int jj = (tid & 7) * 4;                       // output col base
        int n0 = blockIdx.x * 128 + g * 4;
        int m0 = n0 + 0 < N_NODES ? n0 + 0 : N_NODES - 1;
        int m1 = n0 + 1 < N_NODES ? n0 + 1 : N_NODES - 1;
        int m2 = n0 + 2 < N_NODES ? n0 + 2 : N_NODES - 1;
        int m3 = n0 + 3 < N_NODES ? n0 + 3 : N_NODES - 1;
        const float4* f0p = reinterpret_cast<const float4*>(feat + (size_t)m0 * IN_DIM);
        const float4* f1p = reinterpret_cast<const float4*>(feat + (size_t)m1 * IN_DIM);
        const float4* f2p = reinterpret_cast<const float4*>(feat + (size_t)m2 * IN_DIM);
        const float4* f3p = reinterpret_cast<const float4*>(feat + (size_t)m3 * IN_DIM);
        unsigned long long a0x = 0, a0y = 0, a1x = 0, a1y = 0;
        unsigned long long a2x = 0, a2y = 0, a3x = 0, a3y = 0;
        #pragma unroll 4
        for (int k4 = 0; k4 < IN_DIM / 4; k4++) {
            float4 f0 = f0p[k4], f1 = f1p[k4], f2 = f2p[k4], f3 = f3p[k4];
            #pragma unroll
            for (int u = 0; u < 4; u++) {
                ulonglong2 w2 = *reinterpret_cast<const ulonglong2*>(
                    &sW[(k4 * 4 + u) * HID + jj]);
                float e0 = (u == 0) ? f0.x : (u == 1) ? f0.y : (u == 2) ? f0.z : f0.w;
                float e1 = (u == 0) ? f1.x : (u == 1) ? f1.y : (u == 2) ? f1.z : f1.w;
                float e2 = (u == 0) ? f2.x : (u == 1) ? f2.y : (u == 2) ? f2.z : f2.w;
                float e3 = (u == 0) ? f3.x : (u == 1) ? f3.y : (u == 2) ? f3.z : f3.w;
                unsigned long long p0 = bcast2(e0), p1 = bcast2(e1);
                unsigned long long p2 = bcast2(e2), p3 = bcast2(e3);
                ffma2(a0x, p0, w2.x); ffma2(a0y, p0, w2.y);
                ffma2(a1x, p1, w2.x); ffma2(a1y, p1, w2.y);
                ffma2(a2x, p2, w2.x); ffma2(a2y, p2, w2.y);
                ffma2(a3x, p3, w2.x); ffma2(a3y, p3, w2.y);
            }
        }
        unsigned lo, hi;
        #define STORE_NODE(nd, ax, ay) do {                                    \
            if (n0 + nd < N_NODES) {                                           \
                asm("mov.b64 {%0, %1}, %2;" : "=r"(lo), "=r"(hi) : "l"(ax));   \
                float r0 = __uint_as_float(lo), r1 = __uint_as_float(hi);      \
                asm("mov.b64 {%0, %1}, %2;" : "=r"(lo), "=r"(hi) : "l"(ay));   \
                float r2 = __uint_as_float(lo), r3 = __uint_as_float(hi);      \
                half2 q0 = __floats2half2_rn(r0, r1);                          \
                half2 q1 = __floats2half2_rn(r2, r3);                          \
                uint2 pk;                                                      \
                pk.x = *reinterpret_cast<unsigned*>(&q0);                      \
                pk.y = *reinterpret_cast<unsigned*>(&q1);                      \
                *reinterpret_cast<uint2*>(h1 + (size_t)(n0 + nd) * HID + jj) = pk; \
            }                                                                  \
        } while (0)
        STORE_NODE(0, a0x, a0y);
        STORE_NODE(1, a1x, a1y);
        STORE_NODE(2, a2x, a2y);
        STORE_NODE(3, a3x, a3y);
        #undef STORE_NODE
    } else {
        int i = (blockIdx.x - GEMM1_BLOCKS) * 256 + tid;
        if (i >= N_EDGES / 4) return;
        int4 s4 = reinterpret_cast<const int4*>(src)[i];
        int4 d4 = reinterpret_cast<const int4*>(dst)[i];
        int4 r4 = reinterpret_cast<const int4*>(rank)[i];
        // no atomics: position = bucket offset + precomputed rank
        bin[__ldg(off + d4.x) + r4.x] = s4.x;
        bin[__ldg(off + d4.y) + r4.y] = s4.y;
        bin[__ldg(off + d4.z) + r4.z] = s4.z;
        bin[__ldg(off + d4.w) + r4.w] = s4.w;
    }
}

// ---------------- agg1 + finalize1 + gemm2: one warp per node ----------------
// 8 edge-slots x 4 chunk-lanes; each lane loads 16B = 8 halfs of the 64B row.
__global__ void agg1g2_kernel(const __half* __restrict__ h1,
                              const int* __restrict__ bin,
                              const int* __restrict__ off,
                              const int* __restrict__ cnt,
                              const float* __restrict__ b1,
                              const float* __restrict__ W2,
                              __half* __restrict__ h2) {
    __shared__ float sW[HID * OUT];     // 1.5 KB
    __shared__ float sx[8][HID];
    int tid = threadIdx.x;
    for (int i = tid; i < HID * OUT; i += 256) sW[i] = W2[i];
    __syncthreads();
    int w = tid >> 5, lane = tid & 31;
    int node = blockIdx.x * 8 + w;
    if (node >= N_NODES) return;
    int eg = lane >> 2;       // 0..7 edge slot
    int c  = lane & 3;        // 16B chunk
    int start = off[node], n = cnt[node];
    float4 alo = make_float4(0.f, 0.f, 0.f, 0.f);
    float4 ahi = make_float4(0.f, 0.f, 0.f, 0.f);
    for (int i = eg; i < n; i += 8) {
        int s = __ldg(bin + start + i);
        uint4 v = *reinterpret_cast<const uint4*>(h1 + (size_t)s * HID + c * 8);
        float2 f0 = __half22float2(*reinterpret_cast<half2*>(&v.x));
        float2 f1 = __half22float2(*reinterpret_cast<half2*>(&v.y));
        float2 f2 = __half22float2(*reinterpret_cast<half2*>(&v.z));
        float2 f3 = __half22float2(*reinterpret_cast<half2*>(&v.w));
        alo.x += f0.x; alo.y += f0.y; alo.z += f1.x; alo.w += f1.y;
        ahi.x += f2.x; ahi.y += f2.y; ahi.z += f3.x; ahi.w += f3.y;
    }
    #pragma unroll
    for (int d = 4; d < 32; d <<= 1) {
        alo.x += __shfl_xor_sync(~0u, alo.x, d);
        alo.y += __shfl_xor_sync(~0u, alo.y, d);
        alo.z += __shfl_xor_sync(~0u, alo.z, d);
        alo.w += __shfl_xor_sync(~0u, alo.w, d);
        ahi.x += __shfl_xor_sync(~0u, ahi.x, d);
        ahi.y += __shfl_xor_sync(~0u, ahi.y, d);
        ahi.z += __shfl_xor_sync(~0u, ahi.z, d);
        ahi.w += __shfl_xor_sync(~0u, ahi.w, d);
    }
    if (eg == 0) {
        float inv = 1.0f / fmaxf((float)n, 1.0f);
        float4 bA = *reinterpret_cast<const float4*>(b1 + c * 8);
        float4 bB = *reinterpret_cast<const float4*>(b1 + c * 8 + 4);
        sx[w][c * 8 + 0] = fmaxf(fmaf(alo.x, inv, bA.x), 0.f);
        sx[w][c * 8 + 1] = fmaxf(fmaf(alo.y, inv, bA.y), 0.f);
        sx[w][c * 8 + 2] = fmaxf(fmaf(alo.z, inv, bA.z), 0.f);
        sx[w][c * 8 + 3] = fmaxf(fmaf(alo.w, inv, bA.w), 0.f);
        sx[w][c * 8 + 4] = fmaxf(fmaf(ahi.x, inv, bB.x), 0.f);
        sx[w][c * 8 + 5] = fmaxf(fmaf(ahi.y, inv, bB.y), 0.f);
        sx[w][c * 8 + 6] = fmaxf(fmaf(ahi.z, inv, bB.z), 0.f);
        sx[w][c * 8 + 7] = fmaxf(fmaf(ahi.w, inv, bB.w), 0.f);
    }
    __syncwarp();
    if (lane < OUT) {
        float a = 0.f;
        #pragma unroll
        for (int k = 0; k < HID; k++)
            a = fmaf(sx[w][k], sW[k * OUT + lane], a);
        h2[(size_t)node * H2P + lane] = __float2half(a);
    }
}

// ---------------- agg2 + finalize2: one warp per node ----------------
__global__ void agg2_kernel(const __half* __restrict__ h2,
                            const int* __restrict__ bin,
                            const int* __restrict__ off,
                            const int* __restrict__ cnt,
                            const float* __restrict__ b2,
                            float* __restrict__ out) {
    int gw = (blockIdx.x * 256 + threadIdx.x) >> 5;   // node
    if (gw >= N_NODES) return;
    int lane = threadIdx.x & 31;
    int eg = lane >> 2;       // 0..7 edge slot
    int c  = lane & 3;        // 8B chunk, active c<3
    int start = off[gw], n = cnt[gw];
    float4 acc = make_float4(0.f, 0.f, 0.f, 0.f);
    for (int i = eg; i < n; i += 8) {
        int s = __ldg(bin + start + i);
        if (c < 3) {
            uint2 v = *reinterpret_cast<const uint2*>(h2 + (size_t)s * H2P + c * 4);
            float2 f0 = __half22float2(*reinterpret_cast<half2*>(&v.x));
            float2 f1 = __half22float2(*reinterpret_cast<half2*>(&v.y));
            acc.x += f0.x; acc.y += f0.y; acc.z += f1.x; acc.w += f1.y;
        }
    }
    #pragma unroll
    for (int d = 4; d < 32; d <<= 1) {
        acc.x += __shfl_xor_sync(~0u, acc.x, d);
        acc.y += __shfl_xor_sync(~0u, acc.y, d);
        acc.z += __shfl_xor_sync(~0u, acc.z, d);
        acc.w += __shfl_xor_sync(~0u, acc.w, d);
    }
    if (eg == 0 && c < 3) {
        float inv = 1.0f / fmaxf((float)n, 1.0f);
        float4 bb = *reinterpret_cast<const float4*>(b2 + c * 4);
        float4 r;
        r.x = fmaxf(fmaf(acc.x, inv, bb.x), 0.f);
        r.y = fmaxf(fmaf(acc.y, inv, bb.y), 0.f);
        r.z = fmaxf(fmaf(acc.z, inv, bb.z), 0.f);
        r.w = fmaxf(fmaf(acc.w, inv, bb.w), 0.f);
        *reinterpret_cast<float4*>(out + (size_t)gw * OUT + c * 4) = r;
    }
}

// ---------------- launch ----------------
extern "C" void kernel_launch(void* const* d_in, const int* in_sizes, int n_in,
                              void* d_out, int out_size) {
    const float* feat = (const float*)d_in[0];
    const int*   src  = (const int*)  d_in[1];
    const int*   dst  = (const int*)  d_in[2];
    const float* W1   = (const float*)d_in[3];
    const float* b1   = (const float*)d_in[4];
    const float* W2   = (const float*)d_in[5];
    const float* b2   = (const float*)d_in[6];
    float* out = (float*)d_out;

    void *p_h1, *p_h2, *p_cnt, *p_off, *p_rank, *p_bin, *p_part;
    cudaGetSymbolAddress(&p_h1, g_h1);
    cudaGetSymbolAddress(&p_h2, g_h2);
    cudaGetSymbolAddress(&p_cnt, g_cnt);
    cudaGetSymbolAddress(&p_off, g_off);
    cudaGetSymbolAddress(&p_rank, g_rank);
    cudaGetSymbolAddress(&p_bin, g_bin);
    cudaGetSymbolAddress(&p_part, g_part);
    __half* h1 = (__half*)p_h1;
    __half* h2 = (__half*)p_h2;
    int* cnt  = (int*)p_cnt;
    int* off  = (int*)p_off;
    int* rank = (int*)p_rank;
    int* bin  = (int*)p_bin;
    int* part = (int*)p_part;

    cudaMemsetAsync(p_cnt, 0, sizeof(int) * N_NODES, 0);

    // CSR: count(+rank) -> scan (2 kernels)
    count_kernel<<<EV_BLOCKS, 256>>>(dst, cnt, rank);
    scanA_kernel<<<N_SCANB, SCAN_B>>>(cnt, off, part);
    scanC_kernel<<<N_SCANB, SCAN_B>>>(off, part);

    // gemm1 (register-tiled) overlapped with atomic-free bin
    fusedB_kernel<<<GEMM1_BLOCKS + EV_BLOCKS, 256>>>(feat, W1, h1, src, dst,
                                                     rank, off, bin);

    // layer 1 agg + finalize + gemm2
    agg1g2_kernel<<<(N_NODES + 7) / 8, 256>>>(h1, bin, off, cnt, b1, W2, h2);

    // layer 2 agg + finalize
    agg2_kernel<<<(N_NODES * 32 + 255) / 256, 256>>>(h2, bin, off, cnt, b2, out);
}

// round 14
// speedup vs baseline: 1.1025x; 1.1025x over previous
#include <cuda_runtime.h>
#include <cuda_fp16.h>
#include <cstdint>

#define N_NODES 100000
#define N_EDGES 3200000
#define IN_DIM  128
#define HID     32
#define OUT     12
#define H2P     16                                   // padded h2 row (halfs)
#define SCAN_B  1024
#define N_SCANB ((N_NODES + SCAN_B - 1) / SCAN_B)    // 98
#define GEMM1_BLOCKS ((N_NODES + 127) / 128)         // 782 (128 nodes/block)
#define EV_BLOCKS    ((N_EDGES / 4 + 255) / 256)     // 3125 (4 edges/thread)

// ---------------- scratch (allocation-free: __device__ globals) ----------------
__device__ __half         g_h1  [N_NODES * HID];   // feat @ W1 (fp16)
__device__ __half         g_h2  [N_NODES * H2P];   // layer-1 out @ W2 (fp16)
__device__ int            g_cnt [N_NODES];
__device__ int            g_off [N_NODES];
__device__ unsigned short g_rank[N_EDGES];         // edge rank within dst bucket
__device__ int            g_bin [N_EDGES];         // src ids grouped by dst
__device__ int            g_part[128];

// packed f32x2 FMA (sm_10x): d = a*b + c on two fp32 lanes in one FMA-pipe slot
__device__ __forceinline__ void ffma2(unsigned long long& acc,
                                      unsigned long long a,
                                      unsigned long long b) {
    asm("fma.rn.f32x2 %0, %1, %2, %0;" : "+l"(acc) : "l"(a), "l"(b));
}
__device__ __forceinline__ unsigned long long bcast2(float f) {
    unsigned long long r;
    unsigned u = __float_as_uint(f);
    asm("mov.b64 %0, {%1, %1};" : "=l"(r) : "r"(u));
    return r;
}

// ---------------- count + rank: atomicAdd return value IS the bucket rank ----------------
__global__ void count_kernel(const int* __restrict__ dst, int* __restrict__ cnt,
                             unsigned short* __restrict__ rank) {
    int i = blockIdx.x * blockDim.x + threadIdx.x;
    if (i >= N_EDGES / 4) return;
    int4 d4 = reinterpret_cast<const int4*>(dst)[i];
    ushort4 r4;
    r4.x = (unsigned short)atomicAdd(cnt + d4.x, 1);
    r4.y = (unsigned short)atomicAdd(cnt + d4.y, 1);
    r4.z = (unsigned short)atomicAdd(cnt + d4.z, 1);
    r4.w = (unsigned short)atomicAdd(cnt + d4.w, 1);
    reinterpret_cast<ushort4*>(rank)[i] = r4;
}

// ---------------- scanA: per-block exclusive scan + block totals ----------------
__global__ void scanA_kernel(const int* __restrict__ cnt,
                             int* __restrict__ off, int* __restrict__ part) {
    __shared__ int wsum[32];
    int i = blockIdx.x * SCAN_B + threadIdx.x;
    int lane = threadIdx.x & 31, w = threadIdx.x >> 5;
    int v = (i < N_NODES) ? cnt[i] : 0;
    int x = v;
    #pragma unroll
    for (int d = 1; d < 32; d <<= 1) {
        int y = __shfl_up_sync(~0u, x, d);
        if (lane >= d) x += y;
    }
    if (lane == 31) wsum[w] = x;
    __syncthreads();
    if (w == 0) {
        int s = wsum[lane];
        #pragma unroll
        for (int d = 1; d < 32; d <<= 1) {
            int y = __shfl_up_sync(~0u, s, d);
            if (lane >= d) s += y;
        }
        wsum[lane] = s;
    }
    __syncthreads();
    int base = (w > 0) ? wsum[w - 1] : 0;
    if (i < N_NODES) off[i] = base + x - v;
    if (threadIdx.x == SCAN_B - 1) part[blockIdx.x] = base + x;
}

// ---------------- scanC: add prefix of block totals ----------------
__global__ void scanC_kernel(int* __restrict__ off, const int* __restrict__ part) {
    __shared__ int ws[4];
    __shared__ int sbase;
    int t = threadIdx.x;
    if (t < 128) {
        int v = (t < blockIdx.x && t < N_SCANB) ? part[t] : 0;
        #pragma unroll
        for (int d = 16; d >= 1; d >>= 1) v += __shfl_xor_sync(~0u, v, d);
        if ((t & 31) == 0) ws[t >> 5] = v;
    }
    __syncthreads();
    if (t == 0) sbase = ws[0] + ws[1] + ws[2] + ws[3];
    __syncthreads();
    int i = blockIdx.x * SCAN_B + t;
    if (i < N_NODES) off[i] += sbase;
}

// ---------------- fused: gemm1 (4-node register tile, FFMA2) || bin (atomic-free) ----------------
__global__ void fusedB_kernel(const float* __restrict__ feat,
                              const float* __restrict__ W1,
                              __half* __restrict__ h1,
                              const int* __restrict__ src,
                              const int* __restrict__ dst,
                              const unsigned short* __restrict__ rank,
                              const int* __restrict__ off,
                              int* __restrict__ bin) {
    __shared__ float sW[IN_DIM * HID];               // 16 KB (gemm branch only)
    int tid = threadIdx.x;
    if (blockIdx.x < GEMM1_BLOCKS) {
        for (int i = tid; i < IN_DIM * HID; i += 256) sW[i] = W1[i];
        __syncthreads();
        int g  = tid >> 3;                            // 0..31 node group
        int jj = (tid & 7) * 4;                       // output col base
        int n0 = blockIdx.x * 128 + g * 4;
        int m0 = n0 + 0 < N_NODES ? n0 + 0 : N_NODES - 1;
        int m1 = n0 + 1 < N_NODES ? n0 + 1 : N_NODES - 1;
        int m2 = n0 + 2 < N_NODES ? n0 + 2 : N_NODES - 1;
        int m3 = n0 + 3 < N_NODES ? n0 + 3 : N_NODES - 1;
        const float4* f0p = reinterpret_cast<const float4*>(feat + (size_t)m0 * IN_DIM);
        const float4* f1p = reinterpret_cast<const float4*>(feat + (size_t)m1 * IN_DIM);
        const float4* f2p = reinterpret_cast<const float4*>(feat + (size_t)m2 * IN_DIM);
        const float4* f3p = reinterpret_cast<const float4*>(feat + (size_t)m3 * IN_DIM);
        unsigned long long a0x = 0, a0y = 0, a1x = 0, a1y = 0;
        unsigned long long a2x = 0, a2y = 0, a3x = 0, a3y = 0;
        #pragma unroll 4
        for (int k4 = 0; k4 < IN_DIM / 4; k4++) {
            float4 f0 = f0p[k4], f1 = f1p[k4], f2 = f2p[k4], f3 = f3p[k4];
            #pragma unroll
            for (int u = 0; u < 4; u++) {
                ulonglong2 w2 = *reinterpret_cast<const ulonglong2*>(
                    &sW[(k4 * 4 + u) * HID + jj]);
                float e0 = (u == 0) ? f0.x : (u == 1) ? f0.y : (u == 2) ? f0.z : f0.w;
                float e1 = (u == 0) ? f1.x : (u == 1) ? f1.y : (u == 2) ? f1.z : f1.w;
                float e2 = (u == 0) ? f2.x : (u == 1) ? f2.y : (u == 2) ? f2.z : f2.w;
                float e3 = (u == 0) ? f3.x : (u == 1) ? f3.y : (u == 2) ? f3.z : f3.w;
                unsigned long long p0 = bcast2(e0), p1 = bcast2(e1);
                unsigned long long p2 = bcast2(e2), p3 = bcast2(e3);
                ffma2(a0x, p0, w2.x); ffma2(a0y, p0, w2.y);
                ffma2(a1x, p1, w2.x); ffma2(a1y, p1, w2.y);
                ffma2(a2x, p2, w2.x); ffma2(a2y, p2, w2.y);
                ffma2(a3x, p3, w2.x); ffma2(a3y, p3, w2.y);
            }
        }
        unsigned lo, hi;
        #define STORE_NODE(nd, ax, ay) do {                                    \
            if (n0 + nd < N_NODES) {                                           \
                asm("mov.b64 {%0, %1}, %2;" : "=r"(lo), "=r"(hi) : "l"(ax));   \
                float r0 = __uint_as_float(lo), r1 = __uint_as_float(hi);      \
                asm("mov.b64 {%0, %1}, %2;" : "=r"(lo), "=r"(hi) : "l"(ay));   \
                float r2 = __uint_as_float(lo), r3 = __uint_as_float(hi);      \
                half2 q0 = __floats2half2_rn(r0, r1);                          \
                half2 q1 = __floats2half2_rn(r2, r3);                          \
                uint2 pk;                                                      \
                pk.x = *reinterpret_cast<unsigned*>(&q0);                      \
                pk.y = *reinterpret_cast<unsigned*>(&q1);                      \
                *reinterpret_cast<uint2*>(h1 + (size_t)(n0 + nd) * HID + jj) = pk; \
            }                                                                  \
        } while (0)
        STORE_NODE(0, a0x, a0y);
        STORE_NODE(1, a1x, a1y);
        STORE_NODE(2, a2x, a2y);
        STORE_NODE(3, a3x, a3y);
        #undef STORE_NODE
    } else {
        int i = (blockIdx.x - GEMM1_BLOCKS) * 256 + tid;
        if (i >= N_EDGES / 4) return;
        int4 s4 = reinterpret_cast<const int4*>(src)[i];
        int4 d4 = reinterpret_cast<const int4*>(dst)[i];
        ushort4 r4 = reinterpret_cast<const ushort4*>(rank)[i];
        bin[__ldg(off + d4.x) + r4.x] = s4.x;
        bin[__ldg(off + d4.y) + r4.y] = s4.y;
        bin[__ldg(off + d4.z) + r4.z] = s4.z;
        bin[__ldg(off + d4.w) + r4.w] = s4.w;
    }
}

// ---------------- agg1 + finalize1 + gemm2: one warp per node, 2x unrolled ----------------
// 8 edge-slots x 4 chunk-lanes; two independent edges per step for MLP.
__global__ void agg1g2_kernel(const __half* __restrict__ h1,
                              const int* __restrict__ bin,
                              const int* __restrict__ off,
                              const int* __restrict__ cnt,
                              const float* __restrict__ b1,
                              const float* __restrict__ W2,
                              __half* __restrict__ h2) {
    __shared__ float sW[HID * OUT];     // 1.5 KB
    __shared__ float sx[8][HID];
    int tid = threadIdx.x;
    for (int i = tid; i < HID * OUT; i += 256) sW[i] = W2[i];
    __syncthreads();
    int w = tid >> 5, lane = tid & 31;
    int node = blockIdx.x * 8 + w;
    if (node >= N_NODES) return;
    int eg = lane >> 2;       // 0..7 edge slot
    int c  = lane & 3;        // 16B chunk
    int start = off[node], n = cnt[node];
    float4 alo = make_float4(0.f, 0.f, 0.f, 0.f);
    float4 ahi = make_float4(0.f, 0.f, 0.f, 0.f);
    int i = eg;
    for (; i + 8 < n; i += 16) {
        int s0 = __ldg(bin + start + i);
        int s1 = __ldg(bin + start + i + 8);
        uint4 v0 = *reinterpret_cast<const uint4*>(h1 + (size_t)s0 * HID + c * 8);
        uint4 v1 = *reinterpret_cast<const uint4*>(h1 + (size_t)s1 * HID + c * 8);
        float2 a = __half22float2(*reinterpret_cast<half2*>(&v0.x));
        float2 b = __half22float2(*reinterpret_cast<half2*>(&v0.y));
        float2 cc = __half22float2(*reinterpret_cast<half2*>(&v0.z));
        float2 d = __half22float2(*reinterpret_cast<half2*>(&v0.w));
        alo.x += a.x; alo.y += a.y; alo.z += b.x; alo.w += b.y;
        ahi.x += cc.x; ahi.y += cc.y; ahi.z += d.x; ahi.w += d.y;
        a = __half22float2(*reinterpret_cast<half2*>(&v1.x));
        b = __half22float2(*reinterpret_cast<half2*>(&v1.y));
        cc = __half22float2(*reinterpret_cast<half2*>(&v1.z));
        d = __half22float2(*reinterpret_cast<half2*>(&v1.w));
        alo.x += a.x; alo.y += a.y; alo.z += b.x; alo.w += b.y;
        ahi.x += cc.x; ahi.y += cc.y; ahi.z += d.x; ahi.w += d.y;
    }
    if (i < n) {
        int s0 = __ldg(bin + start + i);
        uint4 v0 = *reinterpret_cast<const uint4*>(h1 + (size_t)s0 * HID + c * 8);
        float2 a = __half22float2(*reinterpret_cast<half2*>(&v0.x));
        float2 b = __half22float2(*reinterpret_cast<half2*>(&v0.y));
        float2 cc = __half22float2(*reinterpret_cast<half2*>(&v0.z));
        float2 d = __half22float2(*reinterpret_cast<half2*>(&v0.w));
        alo.x += a.x; alo.y += a.y; alo.z += b.x; alo.w += b.y;
        ahi.x += cc.x; ahi.y += cc.y; ahi.z += d.x; ahi.w += d.y;
    }
    #pragma unroll
    for (int d = 4; d < 32; d <<= 1) {
        alo.x += __shfl_xor_sync(~0u, alo.x, d);
        alo.y += __shfl_xor_sync(~0u, alo.y, d);
        alo.z += __shfl_xor_sync(~0u, alo.z, d);
        alo.w += __shfl_xor_sync(~0u, alo.w, d);
        ahi.x += __shfl_xor_sync(~0u, ahi.x, d);
        ahi.y += __shfl_xor_sync(~0u, ahi.y, d);
        ahi.z += __shfl_xor_sync(~0u, ahi.z, d);
        ahi.w += __shfl_xor_sync(~0u, ahi.w, d);
    }
    if (eg == 0) {
        float inv = 1.0f / fmaxf((float)n, 1.0f);
        float4 bA = *reinterpret_cast<const float4*>(b1 + c * 8);
        float4 bB = *reinterpret_cast<const float4*>(b1 + c * 8 + 4);
        sx[w][c * 8 + 0] = fmaxf(fmaf(alo.x, inv, bA.x), 0.f);
        sx[w][c * 8 + 1] = fmaxf(fmaf(alo.y, inv, bA.y), 0.f);
        sx[w][c * 8 + 2] = fmaxf(fmaf(alo.z, inv, bA.z), 0.f);
        sx[w][c * 8 + 3] = fmaxf(fmaf(alo.w, inv, bA.w), 0.f);
        sx[w][c * 8 + 4] = fmaxf(fmaf(ahi.x, inv, bB.x), 0.f);
        sx[w][c * 8 + 5] = fmaxf(fmaf(ahi.y, inv, bB.y), 0.f);
        sx[w][c * 8 + 6] = fmaxf(fmaf(ahi.z, inv, bB.z), 0.f);
        sx[w][c * 8 + 7] = fmaxf(fmaf(ahi.w, inv, bB.w), 0.f);
    }
    __syncwarp();
    if (lane < OUT) {
        float a = 0.f;
        #pragma unroll
        for (int k = 0; k < HID; k++)
            a = fmaf(sx[w][k], sW[k * OUT + lane], a);
        h2[(size_t)node * H2P + lane] = __float2half(a);
    }
}

// ---------------- agg2 + finalize2: one warp per node, 2x unrolled ----------------
__global__ void agg2_kernel(const __half* __restrict__ h2,
                            const int* __restrict__ bin,
                            const int* __restrict__ off,
                            const int* __restrict__ cnt,
                            const float* __restrict__ b2,
                            float* __restrict__ out) {
    int gw = (blockIdx.x * 256 + threadIdx.x) >> 5;   // node
    if (gw >= N_NODES) return;
    int lane = threadIdx.x & 31;
    int eg = lane >> 2;       // 0..7 edge slot
    int c  = lane & 3;        // 8B chunk, active c<3
    int start = off[gw], n = cnt[gw];
    float4 acc = make_float4(0.f, 0.f, 0.f, 0.f);
    int i = eg;
    for (; i + 8 < n; i += 16) {
        int s0 = __ldg(bin + start + i);
        int s1 = __ldg(bin + start + i + 8);
        if (c < 3) {
            uint2 v0 = *reinterpret_cast<const uint2*>(h2 + (size_t)s0 * H2P + c * 4);
            uint2 v1 = *reinterpret_cast<const uint2*>(h2 + (size_t)s1 * H2P + c * 4);
            float2 f0 = __half22float2(*reinterpret_cast<half2*>(&v0.x));
            float2 f1 = __half22float2(*reinterpret_cast<half2*>(&v0.y));
            acc.x += f0.x; acc.y += f0.y; acc.z += f1.x; acc.w += f1.y;
            f0 = __half22float2(*reinterpret_cast<half2*>(&v1.x));
            f1 = __half22float2(*reinterpret_cast<half2*>(&v1.y));
            acc.x += f0.x; acc.y += f0.y; acc.z += f1.x; acc.w += f1.y;
        }
    }
    if (i < n && c < 3) {
        int s0 = __ldg(bin + start + i);
        uint2 v0 = *reinterpret_cast<const uint2*>(h2 + (size_t)s0 * H2P + c * 4);
        float2 f0 = __half22float2(*reinterpret_cast<half2*>(&v0.x));
        float2 f1 = __half22float2(*reinterpret_cast<half2*>(&v0.y));
        acc.x += f0.x; acc.y += f0.y; acc.z += f1.x; acc.w += f1.y;
    }
    #pragma unroll
    for (int d = 4; d < 32; d <<= 1) {
        acc.x += __shfl_xor_sync(~0u, acc.x, d);
        acc.y += __shfl_xor_sync(~0u, acc.y, d);
        acc.z += __shfl_xor_sync(~0u, acc.z, d);
        acc.w += __shfl_xor_sync(~0u, acc.w, d);
    }
    if (eg == 0 && c < 3) {
        float inv = 1.0f / fmaxf((float)n, 1.0f);
        float4 bb = *reinterpret_cast<const float4*>(b2 + c * 4);
        float4 r;
        r.x = fmaxf(fmaf(acc.x, inv, bb.x), 0.f);
        r.y = fmaxf(fmaf(acc.y, inv, bb.y), 0.f);
        r.z = fmaxf(fmaf(acc.z, inv, bb.z), 0.f);
        r.w = fmaxf(fmaf(acc.w, inv, bb.w), 0.f);
        *reinterpret_cast<float4*>(out + (size_t)gw * OUT + c * 4) = r;
    }
}

// ---------------- launch ----------------
extern "C" void kernel_launch(void* const* d_in, const int* in_sizes, int n_in,
                              void* d_out, int out_size) {
    const float* feat = (const float*)d_in[0];
    const int*   src  = (const int*)  d_in[1];
    const int*   dst  = (const int*)  d_in[2];
    const float* W1   = (const float*)d_in[3];
    const float* b1   = (const float*)d_in[4];
    const float* W2   = (const float*)d_in[5];
    const float* b2   = (const float*)d_in[6];
    float* out = (float*)d_out;

    void *p_h1, *p_h2, *p_cnt, *p_off, *p_rank, *p_bin, *p_part;
    cudaGetSymbolAddress(&p_h1, g_h1);
    cudaGetSymbolAddress(&p_h2, g_h2);
    cudaGetSymbolAddress(&p_cnt, g_cnt);
    cudaGetSymbolAddress(&p_off, g_off);
    cudaGetSymbolAddress(&p_rank, g_rank);
    cudaGetSymbolAddress(&p_bin, g_bin);
    cudaGetSymbolAddress(&p_part, g_part);
    __half* h1 = (__half*)p_h1;
    __half* h2 = (__half*)p_h2;
    int* cnt  = (int*)p_cnt;
    int* off  = (int*)p_off;
    unsigned short* rank = (unsigned short*)p_rank;
    int* bin  = (int*)p_bin;
    int* part = (int*)p_part;

    cudaMemsetAsync(p_cnt, 0, sizeof(int) * N_NODES, 0);

    // CSR: count(+rank) -> scan (2 kernels)
    count_kernel<<<EV_BLOCKS, 256>>>(dst, cnt, rank);
    scanA_kernel<<<N_SCANB, SCAN_B>>>(cnt, off, part);
    scanC_kernel<<<N_SCANB, SCAN_B>>>(off, part);

    // gemm1 (register-tiled) overlapped with atomic-free bin
    fusedB_kernel<<<GEMM1_BLOCKS + EV_BLOCKS, 256>>>(feat, W1, h1, src, dst,
                                                     rank, off, bin);

    // layer 1 agg + finalize + gemm2
    agg1g2_kernel<<<(N_NODES + 7) / 8, 256>>>(h1, bin, off, cnt, b1, W2, h2);

    // layer 2 agg + finalize
    agg2_kernel<<<(N_NODES * 32 + 255) / 256, 256>>>(h2, bin, off, cnt, b2, out);
}